// round 5
// baseline (speedup 1.0000x reference)
#include <cuda_runtime.h>
#include <cuda_bf16.h>
#include <cstdint>

// Problem shape (fixed by the dataset)
#define B_ 8
#define T_ 4096
#define F_ 512
#define ROWS_ (B_ * T_)

#define GRID_ 296          // 2 CTAs per SM (148+ SMs); all co-resident
#define BLK_  1024

// Scratch (no allocations allowed) — device globals.
__device__ float g_z[ROWS_];       // linear scores (pre-sigmoid; monotone-equivalent for peaks)
__device__ int   g_pos[ROWS_];     // compaction destination per row, -1 if not a peak
__device__ int   g_hlens[B_];      // peak counts per batch
__device__ unsigned g_bar_count = 0;
__device__ unsigned g_bar_gen   = 0;

// Software grid barrier. Safe because __launch_bounds__(1024,2) guarantees
// 2-CTA/SM occupancy and GRID_ (296) <= 2 * SM count, so all CTAs are
// co-resident.
__device__ __forceinline__ void grid_barrier() {
    __syncthreads();
    if (threadIdx.x == 0) {
        unsigned gen = *(volatile unsigned*)&g_bar_gen;
        __threadfence();                       // publish this block's phase writes
        unsigned arr = atomicAdd(&g_bar_count, 1u);
        if (arr == GRID_ - 1) {
            atomicExch(&g_bar_count, 0u);
            __threadfence();
            atomicAdd(&g_bar_gen, 1u);         // release
        } else {
            while (*(volatile unsigned*)&g_bar_gen == gen) { }
        }
        __threadfence();                       // acquire other blocks' writes
    }
    __syncthreads();
}

__global__ void __launch_bounds__(BLK_, 2)
k_fused(const float* __restrict__ feat, const float* __restrict__ W,
        float* __restrict__ out, int out_size) {
    const int tid  = threadIdx.x;
    const int lane = tid & 31;
    const int wid  = tid >> 5;                 // 0..31
    const int bid  = blockIdx.x;

    // W lives in shared memory (frees 16 registers/thread -> 2 CTAs/SM).
    __shared__ float4 s_w[F_ / 4];             // 2 KB
    __shared__ int warp_sums[32];
    __shared__ int warp_incl[32];

    if (tid < F_ / 4)
        s_w[tid] = reinterpret_cast<const float4*>(W)[tid];
    __syncthreads();

    // ------------------------------------------------------------------
    // Phase 1: z[row] = dot(feat[row,:], W). One warp per row, strided.
    {
        for (int row = bid * 32 + wid; row < ROWS_; row += GRID_ * 32) {
            const float4* fr = reinterpret_cast<const float4*>(feat + (size_t)row * F_);
            float s = 0.f;
#pragma unroll
            for (int i = 0; i < 4; i++) {
                float4 a = fr[lane + i * 32];
                float4 w = s_w[lane + i * 32];
                s += a.x * w.x + a.y * w.y + a.z * w.z + a.w * w.w;
            }
#pragma unroll
            for (int o = 16; o > 0; o >>= 1)
                s += __shfl_down_sync(0xFFFFFFFFu, s, o);
            if (lane == 0) g_z[row] = s;
        }
    }

    grid_barrier();

    // ------------------------------------------------------------------
    // Phase 2: blocks 0..7 — peak detect + stable exclusive scan per batch.
    // 1024 threads x 4 elements = 4096.
    if (bid < B_) {
        const int b = bid;
        const float* zb = g_z + b * T_;
        const int t0 = tid * 4;

        int flags[4];
        int cnt = 0;
#pragma unroll
        for (int k = 0; k < 4; k++) {
            int t = t0 + k;
            float c = zb[t];
            float l = (t > 0)      ? zb[t - 1] : c;
            float r = (t < T_ - 1) ? zb[t + 1] : c;
            flags[k] = (c >= l) & (c >= r);
            cnt += flags[k];
        }

        int v = cnt;
#pragma unroll
        for (int o = 1; o < 32; o <<= 1) {
            int n = __shfl_up_sync(0xFFFFFFFFu, v, o);
            if (lane >= o) v += n;
        }
        if (lane == 31) warp_sums[wid] = v;
        __syncthreads();
        if (wid == 0) {
            int s = warp_sums[lane];
#pragma unroll
            for (int o = 1; o < 32; o <<= 1) {
                int n = __shfl_up_sync(0xFFFFFFFFu, s, o);
                if (lane >= o) s += n;
            }
            warp_incl[lane] = s;
        }
        __syncthreads();

        int excl = (v - cnt) + (wid > 0 ? warp_incl[wid - 1] : 0);
#pragma unroll
        for (int k = 0; k < 4; k++) {
            int t = t0 + k;
            g_pos[b * T_ + t] = flags[k] ? excl : -1;
            excl += flags[k];
        }
        if (tid == 0) {
            int hl = warp_incl[31];
            g_hlens[b] = hl;
            if (out_size >= ROWS_ * F_ + B_)
                out[(size_t)ROWS_ * F_ + b] = (float)hl;
        }
    }

    grid_barrier();

    // ------------------------------------------------------------------
    // Phase 3: compaction + zero-fill. EIGHT rows per 1024-thread block
    // per iteration: tid>>7 selects the row (0..7), tid&127 is the float4
    // index within the row (512 floats = exactly 128 float4).
    // Streaming stores (__stcs) keep feat resident in L2 for the gather reads.
    {
        const int sub = tid >> 7;              // 0..7: which row of the group
        const int j   = tid & 127;             // float4 index within row
        const float4 z4 = make_float4(0.f, 0.f, 0.f, 0.f);

        for (int base = bid * 8; base < ROWS_; base += GRID_ * 8) {
            const int row = base + sub;
            const int b = row >> 12;           // T_ = 4096
            const int t = row & (T_ - 1);
            const int p  = g_pos[row];
            const int hl = g_hlens[b];

            if (p >= 0) {
                const float4* s = reinterpret_cast<const float4*>(feat + (size_t)row * F_);
                float4* d = reinterpret_cast<float4*>(out + ((size_t)b * T_ + p) * F_);
                __stcs(&d[j], s[j]);
            }
            if (t >= hl) {
                float4* d = reinterpret_cast<float4*>(out + (size_t)row * F_);
                __stcs(&d[j], z4);
            }
        }
    }
}

extern "C" void kernel_launch(void* const* d_in, const int* in_sizes, int n_in,
                              void* d_out, int out_size) {
    const float* feat = (const float*)d_in[0];
    const float* W    = (const float*)d_in[1];
    float* out        = (float*)d_out;
    k_fused<<<GRID_, BLK_>>>(feat, W, out, out_size);
}

// round 6
// speedup vs baseline: 1.2049x; 1.2049x over previous
#include <cuda_runtime.h>
#include <cuda_bf16.h>
#include <cstdint>

// Problem shape (fixed by the dataset)
#define B_ 8
#define T_ 4096
#define F_ 512
#define ROWS_ (B_ * T_)

#define GRID_ 148          // 1 CTA per SM; all co-resident
#define BLK_  1024

// Scratch (no allocations allowed) — device globals.
__device__ float g_z[ROWS_];       // linear scores (pre-sigmoid; monotone-equivalent for peaks)
__device__ int   g_pos[ROWS_];     // compaction destination per row, -1 if not a peak
__device__ int   g_hlens[B_];      // peak counts per batch
__device__ unsigned g_bar_count = 0;
__device__ unsigned g_bar_gen   = 0;

// Software grid barrier. Safe: GRID_ (148) <= SM count and 1 CTA/SM ensures
// all CTAs co-resident.
__device__ __forceinline__ void grid_barrier() {
    __syncthreads();
    if (threadIdx.x == 0) {
        unsigned gen = *(volatile unsigned*)&g_bar_gen;
        __threadfence();                       // publish this block's phase writes
        unsigned arr = atomicAdd(&g_bar_count, 1u);
        if (arr == GRID_ - 1) {
            atomicExch(&g_bar_count, 0u);
            __threadfence();
            atomicAdd(&g_bar_gen, 1u);         // release
        } else {
            while (*(volatile unsigned*)&g_bar_gen == gen) { }
        }
        __threadfence();                       // acquire other blocks' writes
    }
    __syncthreads();
}

__global__ void __launch_bounds__(BLK_, 1)
k_fused(const float* __restrict__ feat, const float* __restrict__ W,
        float* __restrict__ out, int out_size) {
    const int tid  = threadIdx.x;
    const int lane = tid & 31;
    const int wid  = tid >> 5;                 // 0..31
    const int bid  = blockIdx.x;

    __shared__ int warp_sums[32];
    __shared__ int warp_incl[32];
    __shared__ int s_hl[B_];

    // ------------------------------------------------------------------
    // Phase 1: z[row] = dot(feat[row,:], W). FOUR rows per warp per
    // iteration: 16 independent LDG.128 in flight, 4 independent
    // shfl-reduce chains.
    {
        const float4* w4 = reinterpret_cast<const float4*>(W);
        float4 wreg[4];
#pragma unroll
        for (int i = 0; i < 4; i++) wreg[i] = w4[lane + i * 32];

        for (int row0 = bid * 128 + wid * 4; row0 < ROWS_; row0 += GRID_ * 128) {
            // row0 % 4 == 0 and ROWS_ % 4 == 0, so rows row0..row0+3 all valid.
            const float4* f0 = reinterpret_cast<const float4*>(feat + (size_t)(row0 + 0) * F_);
            const float4* f1 = reinterpret_cast<const float4*>(feat + (size_t)(row0 + 1) * F_);
            const float4* f2 = reinterpret_cast<const float4*>(feat + (size_t)(row0 + 2) * F_);
            const float4* f3 = reinterpret_cast<const float4*>(feat + (size_t)(row0 + 3) * F_);
            float s0 = 0.f, s1 = 0.f, s2 = 0.f, s3 = 0.f;
#pragma unroll
            for (int i = 0; i < 4; i++) {
                const int idx = lane + i * 32;
                const float4 w = wreg[i];
                float4 a0 = f0[idx];
                float4 a1 = f1[idx];
                float4 a2 = f2[idx];
                float4 a3 = f3[idx];
                s0 += a0.x * w.x + a0.y * w.y + a0.z * w.z + a0.w * w.w;
                s1 += a1.x * w.x + a1.y * w.y + a1.z * w.z + a1.w * w.w;
                s2 += a2.x * w.x + a2.y * w.y + a2.z * w.z + a2.w * w.w;
                s3 += a3.x * w.x + a3.y * w.y + a3.z * w.z + a3.w * w.w;
            }
#pragma unroll
            for (int o = 16; o > 0; o >>= 1) {
                s0 += __shfl_down_sync(0xFFFFFFFFu, s0, o);
                s1 += __shfl_down_sync(0xFFFFFFFFu, s1, o);
                s2 += __shfl_down_sync(0xFFFFFFFFu, s2, o);
                s3 += __shfl_down_sync(0xFFFFFFFFu, s3, o);
            }
            if (lane == 0) {
                g_z[row0 + 0] = s0;
                g_z[row0 + 1] = s1;
                g_z[row0 + 2] = s2;
                g_z[row0 + 3] = s3;
            }
        }
    }

    grid_barrier();

    // ------------------------------------------------------------------
    // Phase 2: blocks 0..7 — peak detect + stable exclusive scan per batch.
    // 1024 threads x 4 elements = 4096.
    if (bid < B_) {
        const int b = bid;
        const float* zb = g_z + b * T_;
        const int t0 = tid * 4;

        int flags[4];
        int cnt = 0;
#pragma unroll
        for (int k = 0; k < 4; k++) {
            int t = t0 + k;
            float c = zb[t];
            float l = (t > 0)      ? zb[t - 1] : c;
            float r = (t < T_ - 1) ? zb[t + 1] : c;
            flags[k] = (c >= l) & (c >= r);
            cnt += flags[k];
        }

        int v = cnt;
#pragma unroll
        for (int o = 1; o < 32; o <<= 1) {
            int n = __shfl_up_sync(0xFFFFFFFFu, v, o);
            if (lane >= o) v += n;
        }
        if (lane == 31) warp_sums[wid] = v;
        __syncthreads();
        if (wid == 0) {
            int s = warp_sums[lane];
#pragma unroll
            for (int o = 1; o < 32; o <<= 1) {
                int n = __shfl_up_sync(0xFFFFFFFFu, s, o);
                if (lane >= o) s += n;
            }
            warp_incl[lane] = s;
        }
        __syncthreads();

        int excl = (v - cnt) + (wid > 0 ? warp_incl[wid - 1] : 0);
#pragma unroll
        for (int k = 0; k < 4; k++) {
            int t = t0 + k;
            g_pos[b * T_ + t] = flags[k] ? excl : -1;
            excl += flags[k];
        }
        if (tid == 0) {
            int hl = warp_incl[31];
            g_hlens[b] = hl;
            if (out_size >= ROWS_ * F_ + B_)
                out[(size_t)ROWS_ * F_ + b] = (float)hl;
        }
    }

    grid_barrier();

    // ------------------------------------------------------------------
    // Phase 3: compaction + zero-fill. 1024 threads = 8 groups of 128;
    // each group copies FOUR rows per iteration (32 rows/block/iter):
    // batched g_pos loads, then 4 independent source LDG.128, then stores.
    // Streaming stores (__stcs) keep feat resident in L2 for the gathers.
    {
        if (tid < B_) s_hl[tid] = g_hlens[tid];
        __syncthreads();

        const int sub = tid >> 7;              // 0..7: group id
        const int j   = tid & 127;             // float4 index within row
        const float4 z4 = make_float4(0.f, 0.f, 0.f, 0.f);

        for (int base = bid * 32 + sub * 4; base < ROWS_; base += GRID_ * 32) {
            // base % 4 == 0 and ROWS_ % 4 == 0 -> rows base..base+3 valid.
            int p[4], tt[4], bb[4];
#pragma unroll
            for (int k = 0; k < 4; k++) {
                const int row = base + k;
                p[k]  = g_pos[row];
                bb[k] = row >> 12;             // T_ = 4096
                tt[k] = row & (T_ - 1);
            }
            float4 v[4];
#pragma unroll
            for (int k = 0; k < 4; k++) {
                if (p[k] >= 0)
                    v[k] = reinterpret_cast<const float4*>(feat + (size_t)(base + k) * F_)[j];
            }
#pragma unroll
            for (int k = 0; k < 4; k++) {
                if (p[k] >= 0) {
                    float4* d = reinterpret_cast<float4*>(out + ((size_t)bb[k] * T_ + p[k]) * F_);
                    __stcs(&d[j], v[k]);
                }
                if (tt[k] >= s_hl[bb[k]]) {
                    float4* d = reinterpret_cast<float4*>(out + (size_t)(base + k) * F_);
                    __stcs(&d[j], z4);
                }
            }
        }
    }
}

extern "C" void kernel_launch(void* const* d_in, const int* in_sizes, int n_in,
                              void* d_out, int out_size) {
    const float* feat = (const float*)d_in[0];
    const float* W    = (const float*)d_in[1];
    float* out        = (float*)d_out;
    k_fused<<<GRID_, BLK_>>>(feat, W, out, out_size);
}